// round 14
// baseline (speedup 1.0000x reference)
#include <cuda_runtime.h>
#include <cuda_fp16.h>
#include <stdint.h>
#include <math.h>

// Fixed shapes
#define CDIM   64
#define HW     4096                 // 64*64
#define KCODES 512
#define NPTS   131072               // 32*4096
#define NQ     (NPTS*CDIM)          // 8388608
// Output layout: [loss(1) | quantized(NQ) | perplexity(1) | indices(NPTS)]
#define QOFF   1
#define POFF   (1+NQ)
#define IOFF   (2+NQ)

#define TPB      256                // 8 warps
#define PTS_WARP 16
#define PTS_CTA  128
#define NCTA     (NPTS/PTS_CTA)     // 1024
#define NCT      (KCODES/8)         // 64 code tiles of 8
#define CAP      20                 // candidate slots per point

// certified slack coefficient: 2 * 2^-10 * 1.01 * 1.3 ≈ 2.6/1024
#define TE_COEF  (2.6f/1024.0f)

// B hi-fragments: [ct][qq(0..1)][lane] uint4 (+2 tiles pad for prefetch)
__device__ uint4  g_Bh[(NCT+2)*2*32];
__device__ float4 g_ET[KCODES*16];     // row-major codebook: eT[k][c], float4
__device__ float  g_se2[KCODES];
__device__ int    g_counts[KCODES];
__device__ float  g_loss;
__device__ int    g_done;

// dynamic smem layout (float units)
#define ZB_OFF    0          // zbuf[128][68]
#define SE2_OFF   8704       // [512]
#define SCQ_OFF   9216       // [128*CAP] float
#define SCK_OFF   11776      // [128*CAP] int
#define SHIST_OFF 14336      // [512] int
#define SCNT_OFF  14848      // [128] int
#define SBQ_OFF   14976      // [128]
#define SZQ_OFF   15104      // [128]
#define WRED_OFF  15232      // [8]
#define SEMAX_OFF 15240      // [8]
#define SM_FLOATS 15248
#define SMEM_BYTES (SM_FLOATS*4)

__device__ __forceinline__ unsigned packh2(float x, float y) {
    __half2 h = __floats2half2_rn(x, y);
    return *(unsigned*)&h;
}

#define MMA_F16(d0,d1,d2,d3, a0,a1,a2,a3, b0,b1)                               \
    asm("mma.sync.aligned.m16n8k16.row.col.f32.f16.f16.f32 "                   \
        "{%0,%1,%2,%3}, {%4,%5,%6,%7}, {%8,%9}, {%0,%1,%2,%3};"                \
        : "+f"(d0), "+f"(d1), "+f"(d2), "+f"(d3)                               \
        : "r"(a0), "r"(a1), "r"(a2), "r"(a3), "r"(b0), "r"(b1))

// ---------------- prep: Bh fragments, eT transpose, se2, zeros ---------------
__global__ void __launch_bounds__(256)
vq_prep(const float* __restrict__ emb) {
    int id = blockIdx.x * 256 + threadIdx.x;
    if (id < NCT*2*32) {
        int ct   = id >> 6;
        int qq   = (id >> 5) & 1;
        int lane = id & 31;
        int g = lane >> 2, t = lane & 3;
        int code = ct*8 + g;
        unsigned v[4];
        #pragma unroll
        for (int comp = 0; comp < 4; comp++) {
            int kb = qq*2 + (comp >> 1);
            int r  = comp & 1;
            int c0 = kb*16 + 2*t + r*8;
            v[comp] = packh2(emb[c0*KCODES + code], emb[(c0+1)*KCODES + code]);
        }
        g_Bh[(ct*2 + qq)*32 + lane] = make_uint4(v[0], v[1], v[2], v[3]);
    } else if (id < NCT*2*32 + KCODES*16) {
        int id2 = id - NCT*2*32;
        int k  = id2 >> 4;
        int c4 = id2 & 15;
        g_ET[k*16 + c4] = make_float4(emb[(c4*4+0)*KCODES + k],
                                      emb[(c4*4+1)*KCODES + k],
                                      emb[(c4*4+2)*KCODES + k],
                                      emb[(c4*4+3)*KCODES + k]);
    } else if (id < NCT*2*32 + KCODES*16 + KCODES) {
        int k = id - NCT*2*32 - KCODES*16;
        float s = 0.0f;
        #pragma unroll 8
        for (int c = 0; c < CDIM; c++) {
            float v = emb[c*KCODES + k];
            s = fmaf(v, v, s);
        }
        g_se2[k] = s;
        g_counts[k] = 0;
        if (k == 0) { g_loss = 0.0f; g_done = 0; }
    }
}

// ---------------- main: screen + certified rescue ----------------------------
__global__ void __launch_bounds__(TPB)
vq_main(const float* __restrict__ x, float* __restrict__ out) {
    extern __shared__ float sm[];
    float* zbuf  = sm + ZB_OFF;
    float* sse2  = sm + SE2_OFF;
    float* scq   = sm + SCQ_OFF;
    int*   sck   = (int*)(sm + SCK_OFF);
    int*   shist = (int*)(sm + SHIST_OFF);
    int*   scnt  = (int*)(sm + SCNT_OFF);
    float* sbq   = sm + SBQ_OFF;
    float* szq   = sm + SZQ_OFF;
    float* wred  = sm + WRED_OFF;
    float* semax = sm + SEMAX_OFF;

    const int tid  = threadIdx.x;
    const int warp = tid >> 5;
    const int lane = tid & 31;
    const int g    = lane >> 2;
    const int t    = lane & 3;
    const int wptg  = warp*16 + g;
    const int wptg8 = wptg + 8;

    shist[tid] = 0; shist[tid + TPB] = 0;
    if (tid < 128) scnt[tid] = 0;
    float s2a = g_se2[tid], s2b = g_se2[tid + TPB];
    sse2[tid] = s2a; sse2[tid + TPB] = s2b;
    float em = fmaxf(s2a, s2b);
    #pragma unroll
    for (int o = 16; o > 0; o >>= 1)
        em = fmaxf(em, __shfl_xor_sync(0xffffffffu, em, o));
    if (lane == 0) semax[warp] = em;

    // ---- A-load: fp16 fragments + stash z in smem + zsq --------------------
    const int p0w = blockIdx.x * PTS_CTA + warp * PTS_WARP;
    const int b   = p0w >> 12;
    const int hw  = p0w & (HW - 1);
    const float* Base = x + (size_t)b * CDIM * HW + hw;

    unsigned ah[16];
    float zsq0 = 0.0f, zsq1 = 0.0f;
    #pragma unroll
    for (int kb = 0; kb < 4; kb++) {
        int cb = kb*16 + 2*t;
        float f00 = Base[g     + (size_t)(cb    ) * HW];
        float f01 = Base[g     + (size_t)(cb + 1) * HW];
        float f10 = Base[g + 8 + (size_t)(cb    ) * HW];
        float f11 = Base[g + 8 + (size_t)(cb + 1) * HW];
        float f20 = Base[g     + (size_t)(cb + 8) * HW];
        float f21 = Base[g     + (size_t)(cb + 9) * HW];
        float f30 = Base[g + 8 + (size_t)(cb + 8) * HW];
        float f31 = Base[g + 8 + (size_t)(cb + 9) * HW];
        zsq0 = fmaf(f00,f00, fmaf(f01,f01, fmaf(f20,f20, fmaf(f21,f21, zsq0))));
        zsq1 = fmaf(f10,f10, fmaf(f11,f11, fmaf(f30,f30, fmaf(f31,f31, zsq1))));
        ah[kb*4+0] = packh2(f00, f01);
        ah[kb*4+1] = packh2(f10, f11);
        ah[kb*4+2] = packh2(f20, f21);
        ah[kb*4+3] = packh2(f30, f31);
        zbuf[wptg *68 + cb    ] = f00;  zbuf[wptg *68 + cb + 1] = f01;
        zbuf[wptg *68 + cb + 8] = f20;  zbuf[wptg *68 + cb + 9] = f21;
        zbuf[wptg8*68 + cb    ] = f10;  zbuf[wptg8*68 + cb + 1] = f11;
        zbuf[wptg8*68 + cb + 8] = f30;  zbuf[wptg8*68 + cb + 9] = f31;
    }
    // full zsq per point (butterfly over the 4 t-threads)
    #pragma unroll
    for (int o = 1; o <= 2; o <<= 1) {
        zsq0 += __shfl_xor_sync(0xffffffffu, zsq0, o);
        zsq1 += __shfl_xor_sync(0xffffffffu, zsq1, o);
    }
    if (t == 0) { szq[wptg] = zsq0; szq[wptg8] = zsq1; }
    __syncthreads();

    float enm = semax[0];
    #pragma unroll
    for (int i = 1; i < 8; i++) enm = fmaxf(enm, semax[i]);
    const float enmax = sqrtf(enm);
    const float te0 = TE_COEF * sqrtf(zsq0) * enmax;
    const float te1 = TE_COEF * sqrtf(zsq1) * enmax;

    // ---- screen: hh-only distances, candidate collection -------------------
    float tb0 = 3.4e38f, tb1 = 3.4e38f;
    const uint4* Bp = g_Bh;

#define PUSH(WPT, Q, K)                                                        \
    { int s_ = atomicAdd(&scnt[WPT], 1);                                       \
      if (s_ < CAP) { scq[(WPT)*CAP + s_] = (Q); sck[(WPT)*CAP + s_] = (K); } }

#define SBODY(CT, BF)                                                          \
    {                                                                          \
        float dA0=0.f,dA1=0.f,dA2=0.f,dA3=0.f;                                 \
        float dB0=0.f,dB1=0.f,dB2=0.f,dB3=0.f;                                 \
        MMA_F16(dA0,dA1,dA2,dA3, ah[0], ah[1], ah[2], ah[3],  BF[0].x, BF[0].y); \
        MMA_F16(dA0,dA1,dA2,dA3, ah[4], ah[5], ah[6], ah[7],  BF[0].z, BF[0].w); \
        MMA_F16(dB0,dB1,dB2,dB3, ah[8], ah[9], ah[10],ah[11], BF[1].x, BF[1].y); \
        MMA_F16(dB0,dB1,dB2,dB3, ah[12],ah[13],ah[14],ah[15], BF[1].z, BF[1].w); \
        int col = (CT)*8 + 2*t;                                                \
        float s0 = sse2[col], s1 = sse2[col+1];                                \
        float q0 = fmaf(-2.0f, dA0 + dB0, s0);                                 \
        float q1 = fmaf(-2.0f, dA1 + dB1, s1);                                 \
        float q2 = fmaf(-2.0f, dA2 + dB2, s0);                                 \
        float q3 = fmaf(-2.0f, dA3 + dB3, s1);                                 \
        tb0 = fminf(tb0, fminf(q0, q1));                                       \
        tb1 = fminf(tb1, fminf(q2, q3));                                       \
        float th0 = tb0 + te0, th1 = tb1 + te1;                                \
        if (q0 <= th0) PUSH(wptg,  q0, col);                                   \
        if (q1 <= th0) PUSH(wptg,  q1, col+1);                                 \
        if (q2 <= th1) PUSH(wptg8, q2, col);                                   \
        if (q3 <= th1) PUSH(wptg8, q3, col+1);                                 \
    }

#define SPREF(CT, BF)                                                          \
    { BF[0] = Bp[(CT)*2 + 0 + lane*0 + ((CT)*2)*0 + 0]; }   // placeholder

    uint4 B0[2], B1[2];
    B0[0] = Bp[(0*2+0)*32 + lane]; B0[1] = Bp[(0*2+1)*32 + lane];
    #pragma unroll 1
    for (int ct = 0; ct < NCT; ct += 2) {
        B1[0] = Bp[((ct+1)*2+0)*32 + lane];
        B1[1] = Bp[((ct+1)*2+1)*32 + lane];
        SBODY(ct, B0);
        B0[0] = Bp[((ct+2)*2+0)*32 + lane];   // ct=62 -> tile 64 = pad, safe
        B0[1] = Bp[((ct+2)*2+1)*32 + lane];
        SBODY(ct+1, B1);
        if (((ct + 2) & 7) == 0) {            // tighten running best every 8 tiles
            #pragma unroll
            for (int o = 1; o <= 2; o <<= 1) {
                tb0 = fminf(tb0, __shfl_xor_sync(0xffffffffu, tb0, o));
                tb1 = fminf(tb1, __shfl_xor_sync(0xffffffffu, tb1, o));
            }
        }
    }
    #pragma unroll
    for (int o = 1; o <= 2; o <<= 1) {
        tb0 = fminf(tb0, __shfl_xor_sync(0xffffffffu, tb0, o));
        tb1 = fminf(tb1, __shfl_xor_sync(0xffffffffu, tb1, o));
    }
    if (t == 0) { sbq[wptg] = tb0; sbq[wptg8] = tb1; }
    __syncthreads();

    // ---- rescue: exact fp32 over candidates (2 lanes per point) ------------
    {
        const int pt   = lane & 15;
        const int half = lane >> 4;
        const int wpt  = warp*16 + pt;
        const float4* zb = (const float4*)(zbuf) + wpt*17;   // 68/4
        const float  thr = sbq[wpt] + TE_COEF * sqrtf(szq[wpt]) * enmax;
        const int    cnt = scnt[wpt];

        float bd = 3.4e38f;
        int   bk = KCODES;
        if (cnt <= CAP) {
            for (int s = half; s < cnt; s += 2) {
                float q = scq[wpt*CAP + s];
                if (q <= thr) {
                    int k = sck[wpt*CAP + s];
                    const float4* er = g_ET + k*16;
                    float d = 0.0f;
                    #pragma unroll
                    for (int i = 0; i < 16; i++) {
                        float4 e4 = er[i];
                        float4 z4 = zb[i];
                        float u0 = e4.x - z4.x, u1 = e4.y - z4.y;
                        float u2 = e4.z - z4.z, u3 = e4.w - z4.w;
                        d = fmaf(u0,u0, fmaf(u1,u1, fmaf(u2,u2, fmaf(u3,u3, d))));
                    }
                    if (d < bd || (d == bd && k < bk)) { bd = d; bk = k; }
                }
            }
        } else {
            // overflow fallback: exact scan of half the codebook
            for (int k = half*256; k < (half+1)*256; k++) {
                const float4* er = g_ET + k*16;
                float d = 0.0f;
                #pragma unroll
                for (int i = 0; i < 16; i++) {
                    float4 e4 = er[i];
                    float4 z4 = zb[i];
                    float u0 = e4.x - z4.x, u1 = e4.y - z4.y;
                    float u2 = e4.z - z4.z, u3 = e4.w - z4.w;
                    d = fmaf(u0,u0, fmaf(u1,u1, fmaf(u2,u2, fmaf(u3,u3, d))));
                }
                if (d < bd || (d == bd && k < bk)) { bd = d; bk = k; }
            }
        }
        // combine the two half-lanes
        float obd = __shfl_xor_sync(0xffffffffu, bd, 16);
        int   obk = __shfl_xor_sync(0xffffffffu, bk, 16);
        if (obd < bd || (obd == bd && obk < bk)) { bd = obd; bk = obk; }

        float lsum = 0.0f;
        if (lane < 16) {
            out[IOFF + p0w + pt] = (float)bk;
            atomicAdd(&shist[bk], 1);
            lsum = bd;
        }
        #pragma unroll
        for (int o = 16; o > 0; o >>= 1)
            lsum += __shfl_down_sync(0xffffffffu, lsum, o);
        if (lane == 0) wred[warp] = lsum;
    }

    __syncthreads();
    { int h = shist[tid];       if (h) atomicAdd(&g_counts[tid], h);
      h     = shist[tid + TPB]; if (h) atomicAdd(&g_counts[tid + TPB], h); }
    if (tid < 8) {
        float v = wred[tid];
        #pragma unroll
        for (int o = 4; o > 0; o >>= 1)
            v += __shfl_down_sync(0xffu, v, o);
        if (tid == 0) atomicAdd(&g_loss, v);
    }
}

// ---------------- gather (+ fused finalize in last CTA) ----------------------
#define GCTA 128
#define GPTS (NPTS/GCTA)
__global__ void __launch_bounds__(256)
vq_gather(const float* __restrict__ emb, float* __restrict__ out) {
    extern __shared__ float sE[];   // [64][512]
    const int tid  = threadIdx.x;
    const int warp = tid >> 5;
    const int lane = tid & 31;
    {
        const float4* e4 = (const float4*)emb;
        float4* s4 = (float4*)sE;
        #pragma unroll
        for (int i = tid; i < CDIM*KCODES/4; i += 256) s4[i] = e4[i];
    }
    __syncthreads();
    const int P0 = blockIdx.x * GPTS;
    #pragma unroll 1
    for (int pp = tid; pp < GPTS; pp += 256) {
        const int p  = P0 + pp;
        const int b  = p >> 12;
        const int hw = p & (HW - 1);
        const int bi = (int)out[IOFF + p];
        float* oq = out + QOFF + (size_t)b * CDIM * HW + hw;
        #pragma unroll 8
        for (int c = 0; c < CDIM; c++)
            oq[(size_t)c * HW] = sE[c * KCODES + bi];
    }

    __syncthreads();
    __threadfence();
    __shared__ int s_rank;
    if (tid == 0) s_rank = atomicAdd(&g_done, 1);
    __syncthreads();
    if (s_rank == GCTA - 1) {
        float v = 0.0f;
        #pragma unroll
        for (int k = tid; k < KCODES; k += 256) {
            float pr = (float)g_counts[k] * (1.0f / (float)NPTS);
            v += pr * logf(pr + 1e-10f);
        }
        #pragma unroll
        for (int o = 16; o > 0; o >>= 1)
            v += __shfl_down_sync(0xffffffffu, v, o);
        if (lane == 0) sE[warp] = v;
        __syncthreads();
        if (tid < 8) {
            float s = sE[tid];
            #pragma unroll
            for (int o = 4; o > 0; o >>= 1)
                s += __shfl_down_sync(0xffu, s, o);
            if (tid == 0) {
                out[0]    = g_loss * (1.25f / (float)NQ);
                out[POFF] = expf(-s);
            }
        }
    }
}

extern "C" void kernel_launch(void* const* d_in, const int* in_sizes, int n_in,
                              void* d_out, int out_size) {
    const float* x   = (const float*)d_in[0];
    const float* emb = (const float*)d_in[1];
    float* out = (float*)d_out;

    cudaFuncSetAttribute(vq_main, cudaFuncAttributeMaxDynamicSharedMemorySize,
                         SMEM_BYTES);
    cudaFuncSetAttribute(vq_gather, cudaFuncAttributeMaxDynamicSharedMemorySize,
                         CDIM*KCODES*4);

    vq_prep<<<(NCT*2*32 + KCODES*16 + KCODES + 255)/256, 256>>>(emb);
    vq_main<<<NCTA, TPB, SMEM_BYTES>>>(x, out);
    vq_gather<<<GCTA, 256, CDIM*KCODES*4>>>(emb, out);
}

// round 15
// speedup vs baseline: 23.1444x; 23.1444x over previous
#include <cuda_runtime.h>
#include <cuda_fp16.h>
#include <stdint.h>
#include <math.h>

// Fixed shapes
#define CDIM   64
#define HW     4096                 // 64*64
#define KCODES 512
#define NPTS   131072               // 32*4096
#define NQ     (NPTS*CDIM)          // 8388608
// Output layout: [loss(1) | quantized(NQ) | perplexity(1) | indices(NPTS)]
#define QOFF   1
#define POFF   (1+NQ)
#define IOFF   (2+NQ)

#define TPB      256                // 8 warps
#define PTS_WARP 16
#define PTS_CTA  128
#define NCTA     (NPTS/PTS_CTA)     // 1024
#define NCT      (KCODES/8)         // 64 code tiles of 8

// B fp16 fragments, prep-split hi/lo, fragment order, coalesced:
// [ct][qq(0..3)][lane] uint4.  qq: 0=hi kb0-1, 1=hi kb2-3, 2=lo kb0-1, 3=lo kb2-3
// +2 tiles padding for prefetch overrun.
__device__ uint4 g_B[(NCT+2)*4*32];
__device__ float g_se2[KCODES];
__device__ int   g_counts[KCODES];
__device__ float g_loss;
__device__ int   g_done;

__device__ __forceinline__ unsigned packh2(float x, float y) {
    __half2 h = __floats2half2_rn(x, y);
    return *(unsigned*)&h;
}
// split v into fp16 hi + fp16 lo (v ~= hi + lo, residual ~2^-22 |v|)
__device__ __forceinline__ void split2(float x, float y,
                                       unsigned& hi, unsigned& lo) {
    __half hx = __float2half_rn(x), hy = __float2half_rn(y);
    float  rx = x - __half2float(hx), ry = y - __half2float(hy);
    __half2 h = __halves2half2(hx, hy);
    hi = *(unsigned*)&h;
    lo = packh2(rx, ry);
}

#define MMA_F16(d0,d1,d2,d3, a0,a1,a2,a3, b0,b1)                               \
    asm("mma.sync.aligned.m16n8k16.row.col.f32.f16.f16.f32 "                   \
        "{%0,%1,%2,%3}, {%4,%5,%6,%7}, {%8,%9}, {%0,%1,%2,%3};"                \
        : "+f"(d0), "+f"(d1), "+f"(d2), "+f"(d3)                               \
        : "r"(a0), "r"(a1), "r"(a2), "r"(a3), "r"(b0), "r"(b1))

// ---------------- prep: pack B fp16 hi/lo fragments, se2, zeros --------------
__global__ void __launch_bounds__(256)
vq_prep(const float* __restrict__ emb) {
    int id = blockIdx.x * 256 + threadIdx.x;
    if (id < NCT*4*32) {
        int ct   = id >> 7;
        int qq   = (id >> 5) & 3;
        int lane = id & 31;
        int g = lane >> 2, t = lane & 3;
        int split = qq >> 1, halfp = qq & 1;
        int code  = ct*8 + g;
        unsigned v[4];
        #pragma unroll
        for (int comp = 0; comp < 4; comp++) {
            int kb = halfp*2 + (comp >> 1);
            int r  = comp & 1;
            int c0 = kb*16 + 2*t + r*8;       // b-reg r: K rows 2t(+8), 2t+1(+8)
            float f0 = emb[c0*KCODES + code];
            float f1 = emb[(c0+1)*KCODES + code];
            unsigned hi, lo;
            split2(f0, f1, hi, lo);
            v[comp] = split ? lo : hi;
        }
        g_B[(ct*4 + qq)*32 + lane] = make_uint4(v[0], v[1], v[2], v[3]);
    } else if (id < NCT*4*32 + KCODES) {
        int k = id - NCT*4*32;
        float s = 0.0f;
        #pragma unroll 8
        for (int c = 0; c < CDIM; c++) {
            float v = emb[c*KCODES + k];
            s = fmaf(v, v, s);
        }
        g_se2[k] = s;
        g_counts[k] = 0;
        if (k == 0) { g_loss = 0.0f; g_done = 0; }
    }
}

// ---------------- main: distances + argmin -----------------------------------

#define PREFETCH(CT, BF)                                                       \
    { _Pragma("unroll")                                                        \
      for (int m = 0; m < 4; m++) BF[m] = Bp[((CT)*4 + m)*32 + lane]; }

#define TILE_BODY(CT, BF)                                                      \
    {                                                                          \
        float hh0=0.f,hh1=0.f,hh2=0.f,hh3=0.f;                                 \
        float hl0=0.f,hl1=0.f,hl2=0.f,hl3=0.f;                                 \
        float lh0=0.f,lh1=0.f,lh2=0.f,lh3=0.f;                                 \
        _Pragma("unroll")                                                      \
        for (int kb = 0; kb < 4; kb++) {                                       \
            uint4 H = BF[kb>>1];                                               \
            uint4 L = BF[2 + (kb>>1)];                                         \
            unsigned bh0, bh1, bl0, bl1;                                       \
            if ((kb & 1) == 0) { bh0=H.x; bh1=H.y; bl0=L.x; bl1=L.y; }         \
            else               { bh0=H.z; bh1=H.w; bl0=L.z; bl1=L.w; }         \
            MMA_F16(hh0,hh1,hh2,hh3,                                           \
                    ah[kb*4+0],ah[kb*4+1],ah[kb*4+2],ah[kb*4+3], bh0,bh1);     \
            MMA_F16(hl0,hl1,hl2,hl3,                                           \
                    ah[kb*4+0],ah[kb*4+1],ah[kb*4+2],ah[kb*4+3], bl0,bl1);     \
            MMA_F16(lh0,lh1,lh2,lh3,                                           \
                    al[kb*4+0],al[kb*4+1],al[kb*4+2],al[kb*4+3], bh0,bh1);     \
        }                                                                      \
        float d0 = (hh0 + hl0) + lh0;                                          \
        float d1 = (hh1 + hl1) + lh1;                                          \
        float d2 = (hh2 + hl2) + lh2;                                          \
        float d3 = (hh3 + hl3) + lh3;                                          \
        int col = (CT)*8 + 2*t;                                                \
        float s0 = sse2[col], s1 = sse2[col+1];                                \
        float q0 = fmaf(-2.0f, d0, s0);                                        \
        float q1 = fmaf(-2.0f, d1, s1);                                        \
        float q2 = fmaf(-2.0f, d2, s0);                                        \
        float q3 = fmaf(-2.0f, d3, s1);                                        \
        if (q0 < best0 || (q0 == best0 && col   < bi0)) { best0 = q0; bi0 = col;   } \
        if (q1 < best0 || (q1 == best0 && col+1 < bi0)) { best0 = q1; bi0 = col+1; } \
        if (q2 < best1 || (q2 == best1 && col   < bi1)) { best1 = q2; bi1 = col;   } \
        if (q3 < best1 || (q3 == best1 && col+1 < bi1)) { best1 = q3; bi1 = col+1; } \
    }

__global__ void __launch_bounds__(TPB, 2)
vq_main(const float* __restrict__ x, float* __restrict__ out) {
    __shared__ float sse2[KCODES];
    __shared__ int   shist[KCODES];
    __shared__ float wred[8];

    const int tid  = threadIdx.x;
    const int warp = tid >> 5;
    const int lane = tid & 31;
    const int g    = lane >> 2;     // group (row within A tile / code within B)
    const int t    = lane & 3;      // thread-in-group

    sse2[tid]       = g_se2[tid];
    sse2[tid + TPB] = g_se2[tid + TPB];
    shist[tid] = 0; shist[tid + TPB] = 0;

    // ---- load this warp's 16 points as fp16-split A fragments --------------
    const int p0w = blockIdx.x * PTS_CTA + warp * PTS_WARP;
    const int b   = p0w >> 12;
    const int hw  = p0w & (HW - 1);
    const float* Base = x + (size_t)b * CDIM * HW + hw;

    unsigned ah[16], al[16];
    float zsq0 = 0.0f, zsq1 = 0.0f;
    #pragma unroll
    for (int kb = 0; kb < 4; kb++) {
        int cb = kb*16 + 2*t;
        float f00 = Base[g     + (size_t)(cb    ) * HW];
        float f01 = Base[g     + (size_t)(cb + 1) * HW];
        float f10 = Base[g + 8 + (size_t)(cb    ) * HW];
        float f11 = Base[g + 8 + (size_t)(cb + 1) * HW];
        float f20 = Base[g     + (size_t)(cb + 8) * HW];
        float f21 = Base[g     + (size_t)(cb + 9) * HW];
        float f30 = Base[g + 8 + (size_t)(cb + 8) * HW];
        float f31 = Base[g + 8 + (size_t)(cb + 9) * HW];
        zsq0 = fmaf(f00,f00, fmaf(f01,f01, fmaf(f20,f20, fmaf(f21,f21, zsq0))));
        zsq1 = fmaf(f10,f10, fmaf(f11,f11, fmaf(f30,f30, fmaf(f31,f31, zsq1))));
        split2(f00, f01, ah[kb*4+0], al[kb*4+0]);
        split2(f10, f11, ah[kb*4+1], al[kb*4+1]);
        split2(f20, f21, ah[kb*4+2], al[kb*4+2]);
        split2(f30, f31, ah[kb*4+3], al[kb*4+3]);
    }
    __syncthreads();

    // ---- 64 code tiles; coalesced loads, prefetch distance 2 ---------------
    float best0 = 3.4e38f, best1 = 3.4e38f;
    int   bi0 = 0, bi1 = 0;
    const uint4* Bp = g_B;

    uint4 B0[4], B1[4];
    PREFETCH(0, B0);
    #pragma unroll 1
    for (int ct = 0; ct < NCT; ct += 2) {
        PREFETCH(ct+1, B1);
        TILE_BODY(ct, B0);
        PREFETCH(ct+2, B0);       // ct=62 -> tile 64 = padding, safe
        TILE_BODY(ct+1, B1);
    }

    // ---- reduce across the 4 threads of each group (full butterfly) --------
    #pragma unroll
    for (int off = 1; off <= 2; off <<= 1) {
        float ob0 = __shfl_xor_sync(0xffffffffu, best0, off);
        int   oi0 = __shfl_xor_sync(0xffffffffu, bi0,   off);
        float ob1 = __shfl_xor_sync(0xffffffffu, best1, off);
        int   oi1 = __shfl_xor_sync(0xffffffffu, bi1,   off);
        float oz0 = __shfl_xor_sync(0xffffffffu, zsq0,  off);
        float oz1 = __shfl_xor_sync(0xffffffffu, zsq1,  off);
        if (ob0 < best0 || (ob0 == best0 && oi0 < bi0)) { best0 = ob0; bi0 = oi0; }
        if (ob1 < best1 || (ob1 == best1 && oi1 < bi1)) { best1 = ob1; bi1 = oi1; }
        zsq0 += oz0; zsq1 += oz1;
    }

    // ---- emit indices, hist, loss partial ----------------------------------
    float lsum = 0.0f;
    if (t == 0) {
        out[IOFF + p0w + g]     = (float)bi0;
        out[IOFF + p0w + g + 8] = (float)bi1;
        atomicAdd(&shist[bi0], 1);
        atomicAdd(&shist[bi1], 1);
        lsum = (best0 + zsq0) + (best1 + zsq1);   // true min squared distances
    }
    #pragma unroll
    for (int o = 16; o > 0; o >>= 1)
        lsum += __shfl_down_sync(0xffffffffu, lsum, o);
    if (lane == 0) wred[warp] = lsum;

    __syncthreads();
    // flush hist + loss
    { int h = shist[tid];       if (h) atomicAdd(&g_counts[tid], h);
      h     = shist[tid + TPB]; if (h) atomicAdd(&g_counts[tid + TPB], h); }
    if (tid < 8) {
        float v = wred[tid];
        #pragma unroll
        for (int o = 4; o > 0; o >>= 1)
            v += __shfl_down_sync(0xffu, v, o);
        if (tid == 0) atomicAdd(&g_loss, v);
    }
}

// ---------------- gather (+ fused finalize in last CTA) ----------------------
#define GCTA 128
#define GPTS (NPTS/GCTA)   // 1024 points per CTA
__global__ void __launch_bounds__(256)
vq_gather(const float* __restrict__ emb, float* __restrict__ out) {
    extern __shared__ float sE[];   // [64][512]
    const int tid  = threadIdx.x;
    const int warp = tid >> 5;
    const int lane = tid & 31;
    {
        const float4* e4 = (const float4*)emb;
        float4* s4 = (float4*)sE;
        #pragma unroll
        for (int i = tid; i < CDIM*KCODES/4; i += 256) s4[i] = e4[i];
    }
    __syncthreads();
    const int P0 = blockIdx.x * GPTS;
    #pragma unroll 1
    for (int pp = tid; pp < GPTS; pp += 256) {
        const int p  = P0 + pp;
        const int b  = p >> 12;
        const int hw = p & (HW - 1);
        const int bi = (int)out[IOFF + p];
        float* oq = out + QOFF + (size_t)b * CDIM * HW + hw;
        #pragma unroll 8
        for (int c = 0; c < CDIM; c++)
            oq[(size_t)c * HW] = sE[c * KCODES + bi];
    }

    // ---- last CTA computes loss + perplexity -------------------------------
    __syncthreads();
    __threadfence();
    __shared__ int s_rank;
    if (tid == 0) s_rank = atomicAdd(&g_done, 1);
    __syncthreads();
    if (s_rank == GCTA - 1) {
        float v = 0.0f;
        #pragma unroll
        for (int k = tid; k < KCODES; k += 256) {
            float pr = (float)g_counts[k] * (1.0f / (float)NPTS);
            v += pr * logf(pr + 1e-10f);
        }
        #pragma unroll
        for (int o = 16; o > 0; o >>= 1)
            v += __shfl_down_sync(0xffffffffu, v, o);
        if (lane == 0) sE[warp] = v;
        __syncthreads();
        if (tid < 8) {
            float s = sE[tid];
            #pragma unroll
            for (int o = 4; o > 0; o >>= 1)
                s += __shfl_down_sync(0xffu, s, o);
            if (tid == 0) {
                // loss = q_latent + 0.25*e_latent; both equal mean((q-z)^2)
                out[0]    = g_loss * (1.25f / (float)NQ);
                out[POFF] = expf(-s);
            }
        }
    }
}

extern "C" void kernel_launch(void* const* d_in, const int* in_sizes, int n_in,
                              void* d_out, int out_size) {
    const float* x   = (const float*)d_in[0];
    const float* emb = (const float*)d_in[1];
    float* out = (float*)d_out;

    cudaFuncSetAttribute(vq_gather, cudaFuncAttributeMaxDynamicSharedMemorySize,
                         CDIM*KCODES*4);

    vq_prep<<<(NCT*4*32 + KCODES + 255)/256, 256>>>(emb);
    vq_main<<<NCTA, TPB>>>(x, out);
    vq_gather<<<GCTA, 256, CDIM*KCODES*4>>>(emb, out);
}